// round 8
// baseline (speedup 1.0000x reference)
#include <cuda_runtime.h>
#include <cuda_fp16.h>
#include <math.h>
#include <cstdint>

#define BATCH 16384
#define OBS   512
#define ACT   256
#define NE    16
#define TOPK  4
#define TILE_M 128
#define NCHUNK 4                       // K chunks of 128
#define MAX_CHUNKS (BATCH / TILE_M)

// ---------------- static device scratch ----------------
__device__ int    g_cnt[NE];
__device__ int    g_ridx[NE * BATCH];
__device__ float  g_w[NE * BATCH];
__device__ __half g_scr[(size_t)2 * 4 * BATCH * ACT];     // fp16 scratch [mat][slot][BATCH][ACT]
__device__ __half g_xt[(size_t)BATCH * OBS];              // fp16, k-permuted x
__device__ __half g_wt[(size_t)2 * NE * ACT * OBS];       // fp16, k-permuted weights

struct alignas(16) H8 { __half2 a, b, c, d; };

// m16n8k16 fp16 mma, fp32 accumulate
__device__ __forceinline__ void mma_f16(float* c,
                                        uint32_t a0, uint32_t a1, uint32_t a2, uint32_t a3,
                                        uint32_t b0, uint32_t b1) {
    asm volatile(
        "mma.sync.aligned.m16n8k16.row.col.f32.f16.f16.f32 "
        "{%0,%1,%2,%3}, {%4,%5,%6,%7}, {%8,%9}, {%0,%1,%2,%3};"
        : "+f"(c[0]), "+f"(c[1]), "+f"(c[2]), "+f"(c[3])
        : "r"(a0), "r"(a1), "r"(a2), "r"(a3), "r"(b0), "r"(b1));
}

__device__ __forceinline__ uint32_t smem_u32(const void* p) {
    uint32_t a;
    asm("{ .reg .u64 t; cvta.to.shared.u64 t, %1; cvt.u32.u64 %0, t; }" : "=r"(a) : "l"(p));
    return a;
}
__device__ __forceinline__ void cp16(uint32_t dst, const void* src, int sz) {
    asm volatile("cp.async.cg.shared.global [%0], [%1], 16, %2;"
                 :: "r"(dst), "l"(src), "r"(sz) : "memory");
}
#define CP_COMMIT() asm volatile("cp.async.commit_group;" ::: "memory")
#define CP_WAIT0()  asm volatile("cp.async.wait_group 0;" ::: "memory")

// pack a 16-k group (4 float4s, k contiguous) into permuted fp16:
// [k0,k1,k8,k9, k2,k3,k10,k11, k4,k5,k12,k13, k6,k7,k14,k15]
__device__ __forceinline__ void pack_group(float4 v0, float4 v1, float4 v2, float4 v3,
                                           H8* dst) {
    H8 o0, o1;
    o0.a = __floats2half2_rn(v0.x, v0.y); o0.b = __floats2half2_rn(v2.x, v2.y);
    o0.c = __floats2half2_rn(v0.z, v0.w); o0.d = __floats2half2_rn(v2.z, v2.w);
    o1.a = __floats2half2_rn(v1.x, v1.y); o1.b = __floats2half2_rn(v3.x, v3.y);
    o1.c = __floats2half2_rn(v1.z, v1.w); o1.d = __floats2half2_rn(v3.z, v3.w);
    dst[0] = o0; dst[1] = o1;
}

// ---------------- kernel 1: fused prep ----------------
// blocks [0, 2048): router, warp = 2 rows x 16 experts (thread-per-dot) + x pack.
// blocks [2048, 4096): weight fp16 convert+permute.
__global__ void __launch_bounds__(128) prep_kernel(const float* __restrict__ x,
                                                   const float* __restrict__ rw,
                                                   const float* __restrict__ rb,
                                                   const float* __restrict__ mw,
                                                   const float* __restrict__ lw) {
    const int bx = blockIdx.x;
    if (bx >= 2048) {
        // ---- weight convert: one 16-k group per thread ----
        int flat = (bx - 2048) * 128 + threadIdx.x;  // 262144 = 8192 rows x 32 groups
        int g16 = flat & 31;
        int rowp = flat >> 5;                        // mat*4096 + row
        int mat = rowp >> 12;
        const float4* s4 = (const float4*)((mat ? lw : mw) + (size_t)(rowp & 4095) * OBS + g16 * 16);
        pack_group(s4[0], s4[1], s4[2], s4[3], (H8*)(g_wt + (size_t)rowp * OBS + g16 * 16));
        return;
    }

    // ---- router: lane = r2*16 + e; each lane computes full 512-dot ----
    const int warp = threadIdx.x >> 5;
    const int lane = threadIdx.x & 31;
    const int r2 = lane >> 4;
    const int e  = lane & 15;
    const int b  = bx * 8 + warp * 2 + r2;

    const float4* xp = (const float4*)x + (size_t)b * 128;
    const float4* wp = (const float4*)rw + e * 128;

    float a0 = 0.f, a1 = 0.f, a2 = 0.f, a3 = 0.f;
#pragma unroll 4
    for (int j = 0; j < 32; j++) {
        float4 x0 = xp[4 * j], x1 = xp[4 * j + 1], x2 = xp[4 * j + 2], x3 = xp[4 * j + 3];
        float4 w0 = __ldg(wp + 4 * j),     w1 = __ldg(wp + 4 * j + 1);
        float4 w2 = __ldg(wp + 4 * j + 2), w3 = __ldg(wp + 4 * j + 3);
        a0 = fmaf(x0.x, w0.x, fmaf(x0.y, w0.y, fmaf(x0.z, w0.z, fmaf(x0.w, w0.w, a0))));
        a1 = fmaf(x1.x, w1.x, fmaf(x1.y, w1.y, fmaf(x1.z, w1.z, fmaf(x1.w, w1.w, a1))));
        a2 = fmaf(x2.x, w2.x, fmaf(x2.y, w2.y, fmaf(x2.z, w2.z, fmaf(x2.w, w2.w, a2))));
        a3 = fmaf(x3.x, w3.x, fmaf(x3.y, w3.y, fmaf(x3.z, w3.z, fmaf(x3.w, w3.w, a3))));
    }
    float logit = (a0 + a1) + (a2 + a3) + __ldg(rb + e);

    // pack x row to fp16 (row is L1-hot); lane handles groups e and e+16
#pragma unroll
    for (int gi = 0; gi < 2; gi++) {
        int grp = e + gi * 16;
        const float4* src = xp + grp * 4;
        pack_group(src[0], src[1], src[2], src[3],
                   (H8*)(g_xt + (size_t)b * OBS + grp * 16));
    }

    // softmax over the 16-lane group
    float m = logit;
#pragma unroll
    for (int off = 8; off; off >>= 1) m = fmaxf(m, __shfl_xor_sync(0xffffffffu, m, off));
    float p = expf(logit - m);
    float s = p;
#pragma unroll
    for (int off = 8; off; off >>= 1) s += __shfl_xor_sync(0xffffffffu, s, off);
    float prob = p / s;

    // top-4 within group, lowest-expert tie-break
    const unsigned gmask = r2 ? 0xFFFF0000u : 0x0000FFFFu;
    float cur = prob;
#pragma unroll
    for (int slot = 0; slot < TOPK; slot++) {
        float mx = cur;
#pragma unroll
        for (int off = 8; off; off >>= 1) mx = fmaxf(mx, __shfl_xor_sync(0xffffffffu, mx, off));
        unsigned bal = __ballot_sync(0xffffffffu, cur == mx) & gmask;
        int sel = __ffs(bal) - 1;
        if (lane == sel) {
            int pos = atomicAdd(&g_cnt[e], 1);
            g_ridx[e * BATCH + pos] = b * 4 + slot;
            g_w[e * BATCH + pos]    = prob;
            cur = -1.f;
        }
    }
}

// ---------------- kernel 2: fp16 mma grouped GEMM, K-chunk 128 ----------------
#define ABYTES 32768u                  // 128 rows x 256 B
#define BBYTES 65536u                  // 256 rows x 256 B
#define DYN_SMEM (2 * (ABYTES + BBYTES))   // 196608

__global__ void __launch_bounds__(512, 1)
expert_mma_kernel(const float* __restrict__ mb, const float* __restrict__ lb) {
    const int e   = blockIdx.y;
    const int mat = blockIdx.z;
    const int n   = g_cnt[e];
    const int start = blockIdx.x * TILE_M;
    if (start >= n) return;
    const int mrows = min(TILE_M, n - start);

    __shared__ int   bs[TILE_M];
    __shared__ int   ss[TILE_M];
    __shared__ float ws[TILE_M];
    extern __shared__ char smraw[];
    const uint32_t sb = smem_u32(smraw);

    const int t = threadIdx.x;
    if (t < TILE_M) {
        if (t < mrows) {
            int entry = g_ridx[e * BATCH + start + t];
            bs[t] = entry >> 2; ss[t] = entry & 3;
            ws[t] = g_w[e * BATCH + start + t];
        } else { bs[t] = 0; ss[t] = 0; ws[t] = 0.f; }
    }
    __syncthreads();

    const char* xt = (const char*)g_xt;
    const char* wt = (const char*)(g_wt + (size_t)((mat * NE + e) * ACT) * OBS);

    const int lane = t & 31;
    const int g  = lane >> 2;
    const int tg = lane & 3;
    const int wid = t >> 5;
    const int wm = wid & 3;
    const int wn = wid >> 2;

    auto issue = [&](int kc, int buf) {
        const uint32_t abase = sb + buf * ABYTES;
#pragma unroll
        for (int i = 0; i < 4; i++) {               // A: 2048 quads
            int idx = t + 512 * i;
            int r = idx >> 4, q = idx & 15;
            const char* src = xt + (size_t)bs[r] * 1024 + kc * 256 + q * 16;
            uint32_t d = abase + (uint32_t)(r * 16 + (q ^ ((r & 7) << 1))) * 16u;
            cp16(d, src, (r < mrows) ? 16 : 0);
        }
        const uint32_t bbase = sb + 2 * ABYTES + buf * BBYTES;
#pragma unroll
        for (int i = 0; i < 8; i++) {               // B: 4096 quads
            int idx = t + 512 * i;
            int r = idx >> 4, q = idx & 15;
            const char* src = wt + (size_t)r * 1024 + kc * 256 + q * 16;
            cp16(bbase + (uint32_t)(r * 16 + (q ^ ((r & 7) << 1))) * 16u, src, 16);
        }
    };

    float acc[2][8][4];
#pragma unroll
    for (int im = 0; im < 2; im++)
#pragma unroll
        for (int in = 0; in < 8; in++)
#pragma unroll
            for (int c = 0; c < 4; c++) acc[im][in][c] = 0.f;

    issue(0, 0);
    CP_COMMIT();

    const int sw   = g << 1;
    const int qsub = tg >> 1;
    const int bsel = (tg & 1) * 8;

#pragma unroll 1
    for (int kc = 0; kc < NCHUNK; kc++) {
        const int buf = kc & 1;
        CP_WAIT0();
        __syncthreads();
        if (kc + 1 < NCHUNK) { issue(kc + 1, buf ^ 1); CP_COMMIT(); }

        const char* Ab = smraw + buf * ABYTES;
        const char* Bb = smraw + 2 * ABYTES + buf * BBYTES;

#pragma unroll
        for (int ks = 0; ks < 8; ks++) {
            const int qoff = ((ks * 2 + qsub) ^ sw) * 16 + bsel;
            uint2 U[2], V[2];
#pragma unroll
            for (int im = 0; im < 2; im++) {
                const char* ap = Ab + (wm * 32 + im * 16 + g) * 256 + qoff;
                U[im] = *(const uint2*)ap;
                V[im] = *(const uint2*)(ap + 2048);
            }
#pragma unroll
            for (int in = 0; in < 8; in++) {
                uint2 W = *(const uint2*)(Bb + (wn * 64 + in * 8 + g) * 256 + qoff);
                mma_f16(acc[0][in], U[0].x, V[0].x, U[0].y, V[0].y, W.x, W.y);
                mma_f16(acc[1][in], U[1].x, V[1].x, U[1].y, V[1].y, W.x, W.y);
            }
        }
        __syncthreads();
    }

    // epilogue: w * (acc + bias) -> fp16 slot-indexed scratch (deterministic)
    const float* bias = (mat ? lb : mb) + e * ACT;
    float2 bv[8];
#pragma unroll
    for (int in = 0; in < 8; in++) {
        int c = wn * 64 + in * 8 + 2 * tg;
        bv[in] = make_float2(__ldg(bias + c), __ldg(bias + c + 1));
    }
#pragma unroll
    for (int im = 0; im < 2; im++) {
#pragma unroll
        for (int half = 0; half < 2; half++) {
            int r = wm * 32 + im * 16 + half * 8 + g;
            if (r < mrows) {
                float w = ws[r];
                __half* dst = g_scr + ((size_t)(mat * 4 + ss[r]) * BATCH + bs[r]) * ACT
                            + wn * 64 + 2 * tg;
#pragma unroll
                for (int in = 0; in < 8; in++) {
                    float ox = w * (acc[im][in][half * 2 + 0] + bv[in].x);
                    float oy = w * (acc[im][in][half * 2 + 1] + bv[in].y);
                    *(__half2*)(dst + in * 8) = __floats2half2_rn(ox, oy);
                }
            }
        }
    }
}

// ---------------- kernel 3: combine slots (fp16 scratch), tanh squash ----------------
__global__ void __launch_bounds__(256) finalize_kernel(float* __restrict__ out) {
    const size_t N8 = (size_t)BATCH * ACT / 8;
    const size_t N4 = (size_t)BATCH * ACT / 4;
    size_t i = (size_t)blockIdx.x * 256 + threadIdx.x;
    if (i >= N8) return;
    const uint4* s = (const uint4*)g_scr;
    float4* out4 = (float4*)out;

    float acc[8];
#pragma unroll
    for (int j = 0; j < 8; j++) acc[j] = 0.f;
#pragma unroll
    for (int sl = 0; sl < 4; sl++) {
        uint4 u = s[sl * N8 + i];
        float2 f0 = __half22float2(*(__half2*)&u.x);
        float2 f1 = __half22float2(*(__half2*)&u.y);
        float2 f2 = __half22float2(*(__half2*)&u.z);
        float2 f3 = __half22float2(*(__half2*)&u.w);
        acc[0] += f0.x; acc[1] += f0.y; acc[2] += f1.x; acc[3] += f1.y;
        acc[4] += f2.x; acc[5] += f2.y; acc[6] += f3.x; acc[7] += f3.y;
    }
    out4[2 * i]     = make_float4(acc[0], acc[1], acc[2], acc[3]);
    out4[2 * i + 1] = make_float4(acc[4], acc[5], acc[6], acc[7]);

#pragma unroll
    for (int j = 0; j < 8; j++) acc[j] = 0.f;
#pragma unroll
    for (int sl = 4; sl < 8; sl++) {
        uint4 u = s[sl * N8 + i];
        float2 f0 = __half22float2(*(__half2*)&u.x);
        float2 f1 = __half22float2(*(__half2*)&u.y);
        float2 f2 = __half22float2(*(__half2*)&u.z);
        float2 f3 = __half22float2(*(__half2*)&u.w);
        acc[0] += f0.x; acc[1] += f0.y; acc[2] += f1.x; acc[3] += f1.y;
        acc[4] += f2.x; acc[5] += f2.y; acc[6] += f3.x; acc[7] += f3.y;
    }
#pragma unroll
    for (int j = 0; j < 8; j++) acc[j] = -5.f + 3.5f * (tanhf(acc[j]) + 1.f);
    out4[N4 + 2 * i]     = make_float4(acc[0], acc[1], acc[2], acc[3]);
    out4[N4 + 2 * i + 1] = make_float4(acc[4], acc[5], acc[6], acc[7]);
}

// ---------------- launch ----------------
extern "C" void kernel_launch(void* const* d_in, const int* in_sizes, int n_in,
                              void* d_out, int out_size) {
    const float* x  = (const float*)d_in[0];
    const float* rw = (const float*)d_in[1];
    const float* rb = (const float*)d_in[2];
    const float* mw = (const float*)d_in[3];
    const float* mb = (const float*)d_in[4];
    const float* lw = (const float*)d_in[5];
    const float* lb = (const float*)d_in[6];
    float* out = (float*)d_out;

    cudaFuncSetAttribute(expert_mma_kernel,
                         cudaFuncAttributeMaxDynamicSharedMemorySize, DYN_SMEM);

    void* cntp = nullptr;
    cudaGetSymbolAddress(&cntp, g_cnt);
    cudaMemsetAsync(cntp, 0, sizeof(int) * NE);

    prep_kernel<<<4096, 128>>>(x, rw, rb, mw, lw);

    dim3 g2(MAX_CHUNKS, NE, 2);
    expert_mma_kernel<<<g2, 512, DYN_SMEM>>>(mb, lb);

    finalize_kernel<<<(BATCH * ACT / 8 + 255) / 256, 256>>>(out);
}

// round 9
// speedup vs baseline: 1.1569x; 1.1569x over previous
#include <cuda_runtime.h>
#include <cuda_fp16.h>
#include <math.h>
#include <cstdint>

#define BATCH 16384
#define OBS   512
#define ACT   256
#define NE    16
#define TOPK  4
#define TILE_M 128
#define NCHUNK 4                       // K chunks of 128
#define MAX_CHUNKS (BATCH / TILE_M)

// ---------------- static device scratch ----------------
__device__ int    g_cnt[NE];
__device__ int    g_ridx[NE * BATCH];
__device__ float  g_w[NE * BATCH];
__device__ __half g_scr[(size_t)2 * 4 * BATCH * ACT];     // fp16 scratch [mat][slot][BATCH][ACT]
__device__ __half g_xt[(size_t)BATCH * OBS];              // fp16, k-permuted x
__device__ __half g_wt[(size_t)2 * NE * ACT * OBS];       // fp16, k-permuted weights

struct alignas(16) H8 { __half2 a, b, c, d; };

// m16n8k16 fp16 mma, fp32 accumulate
__device__ __forceinline__ void mma_f16(float* c,
                                        uint32_t a0, uint32_t a1, uint32_t a2, uint32_t a3,
                                        uint32_t b0, uint32_t b1) {
    asm volatile(
        "mma.sync.aligned.m16n8k16.row.col.f32.f16.f16.f32 "
        "{%0,%1,%2,%3}, {%4,%5,%6,%7}, {%8,%9}, {%0,%1,%2,%3};"
        : "+f"(c[0]), "+f"(c[1]), "+f"(c[2]), "+f"(c[3])
        : "r"(a0), "r"(a1), "r"(a2), "r"(a3), "r"(b0), "r"(b1));
}

__device__ __forceinline__ uint32_t smem_u32(const void* p) {
    uint32_t a;
    asm("{ .reg .u64 t; cvta.to.shared.u64 t, %1; cvt.u32.u64 %0, t; }" : "=r"(a) : "l"(p));
    return a;
}
__device__ __forceinline__ void cp16(uint32_t dst, const void* src, int sz) {
    asm volatile("cp.async.cg.shared.global [%0], [%1], 16, %2;"
                 :: "r"(dst), "l"(src), "r"(sz) : "memory");
}
#define CP_COMMIT() asm volatile("cp.async.commit_group;" ::: "memory")
#define CP_WAIT0()  asm volatile("cp.async.wait_group 0;" ::: "memory")

// pack a 16-k group (4 float4s, k contiguous) into permuted fp16:
// [k0,k1,k8,k9, k2,k3,k10,k11, k4,k5,k12,k13, k6,k7,k14,k15]
__device__ __forceinline__ void pack_group(float4 v0, float4 v1, float4 v2, float4 v3,
                                           H8* dst) {
    H8 o0, o1;
    o0.a = __floats2half2_rn(v0.x, v0.y); o0.b = __floats2half2_rn(v2.x, v2.y);
    o0.c = __floats2half2_rn(v0.z, v0.w); o0.d = __floats2half2_rn(v2.z, v2.w);
    o1.a = __floats2half2_rn(v1.x, v1.y); o1.b = __floats2half2_rn(v3.x, v3.y);
    o1.c = __floats2half2_rn(v1.z, v1.w); o1.d = __floats2half2_rn(v3.z, v3.w);
    dst[0] = o0; dst[1] = o1;
}

// ---------------- kernel 0: weight pre-convert (fp16 + k-permute) ----------------
__global__ void __launch_bounds__(256) wconv_kernel(const float* __restrict__ mw,
                                                    const float* __restrict__ lw) {
    int flat = blockIdx.x * 256 + threadIdx.x;   // 8192 rows x 32 groups = 262144
    int g16 = flat & 31;
    int rowp = flat >> 5;                        // mat*4096 + row
    int mat = rowp >> 12;
    const float4* s4 = (const float4*)((mat ? lw : mw) + (size_t)(rowp & 4095) * OBS + g16 * 16);
    pack_group(s4[0], s4[1], s4[2], s4[3], (H8*)(g_wt + (size_t)rowp * OBS + g16 * 16));
}

// ---------------- kernel 1: router (1 row/warp, butterfly) + x pack ----------------
__global__ void __launch_bounds__(128) router_kernel(const float* __restrict__ x,
                                                     const float* __restrict__ rw,
                                                     const float* __restrict__ rb) {
    const int warp = threadIdx.x >> 5;
    const int lane = threadIdx.x & 31;
    const int b = blockIdx.x * 4 + warp;

    // lane owns k-group lane (k = 16*lane .. 16*lane+15)
    const float4* x4 = (const float4*)x + (size_t)b * 128;
    float4 v[4];
#pragma unroll
    for (int i = 0; i < 4; i++) v[i] = x4[4 * lane + i];

    pack_group(v[0], v[1], v[2], v[3], (H8*)(g_xt + (size_t)b * OBS + lane * 16));

    // partial logits, 16 parallel accumulators per lane
    float s[16];
#pragma unroll
    for (int e = 0; e < NE; e++) {
        const float4* w4 = (const float4*)rw + e * 128 + 4 * lane;
        float a = 0.f;
#pragma unroll
        for (int i = 0; i < 4; i++) {
            float4 w = __ldg(w4 + i);
            a = fmaf(v[i].x, w.x, fmaf(v[i].y, w.y, fmaf(v[i].z, w.z, fmaf(v[i].w, w.w, a))));
        }
        s[e] = a;
    }

    // register-folding butterfly: 16 regs over 32 lanes -> expert (lane>>1)&15
#pragma unroll
    for (int round = 0; round < 4; round++) {
        const int bit = 16 >> round;
        const int nreg = 8 >> round;
        bool hi = (lane & bit) != 0;
#pragma unroll
        for (int e = 0; e < 8; e++) {
            if (e < nreg) {
                float send = hi ? s[e] : s[e + nreg];
                float recv = __shfl_xor_sync(0xffffffffu, send, bit);
                float keep = hi ? s[e + nreg] : s[e];
                s[e] = keep + recv;
            }
        }
    }
    float lsum = s[0] + __shfl_xor_sync(0xffffffffu, s[0], 1);
    const int my_e = (lane >> 1) & 15;
    float logit = lsum + __ldg(rb + my_e);

    float m = logit;
#pragma unroll
    for (int off = 16; off; off >>= 1) m = fmaxf(m, __shfl_xor_sync(0xffffffffu, m, off));
    float pexp = expf(logit - m);
    float pc = (lane & 1) ? 0.f : pexp;
#pragma unroll
    for (int off = 16; off; off >>= 1) pc += __shfl_xor_sync(0xffffffffu, pc, off);
    float prob_pair = pexp / pc;
    float prob = __shfl_sync(0xffffffffu, prob_pair, 2 * (lane & 15));

    float cur = (lane < NE) ? prob : -1.f;
#pragma unroll
    for (int slot = 0; slot < TOPK; slot++) {
        float mx = cur;
#pragma unroll
        for (int off = 16; off; off >>= 1) mx = fmaxf(mx, __shfl_xor_sync(0xffffffffu, mx, off));
        unsigned bal = __ballot_sync(0xffffffffu, cur == mx);
        int sel = __ffs(bal) - 1;
        if (lane == sel) {
            int pos = atomicAdd(&g_cnt[lane], 1);
            g_ridx[lane * BATCH + pos] = b * 4 + slot;
            g_w[lane * BATCH + pos]    = prob;
            cur = -1.f;
        }
    }
}

// ---------------- kernel 2: fp16 mma grouped GEMM, K-chunk 128 ----------------
#define ABYTES 32768u                  // 128 rows x 256 B
#define BBYTES 65536u                  // 256 rows x 256 B
#define DYN_SMEM (2 * (ABYTES + BBYTES))   // 196608

__global__ void __launch_bounds__(512, 1)
expert_mma_kernel(const float* __restrict__ mb, const float* __restrict__ lb) {
    const int e   = blockIdx.y;
    const int mat = blockIdx.z;
    const int n   = g_cnt[e];
    const int start = blockIdx.x * TILE_M;
    if (start >= n) return;
    const int mrows = min(TILE_M, n - start);

    __shared__ int   bs[TILE_M];
    __shared__ int   ss[TILE_M];
    __shared__ float ws[TILE_M];
    extern __shared__ char smraw[];
    const uint32_t sb = smem_u32(smraw);

    const int t = threadIdx.x;
    if (t < TILE_M) {
        if (t < mrows) {
            int entry = g_ridx[e * BATCH + start + t];
            bs[t] = entry >> 2; ss[t] = entry & 3;
            ws[t] = g_w[e * BATCH + start + t];
        } else { bs[t] = 0; ss[t] = 0; ws[t] = 0.f; }
    }
    __syncthreads();

    const char* xt = (const char*)g_xt;
    const char* wt = (const char*)(g_wt + (size_t)((mat * NE + e) * ACT) * OBS);

    const int lane = t & 31;
    const int g  = lane >> 2;
    const int tg = lane & 3;
    const int wid = t >> 5;
    const int wm = wid & 3;
    const int wn = wid >> 2;

    auto issue = [&](int kc, int buf) {
        const uint32_t abase = sb + buf * ABYTES;
#pragma unroll
        for (int i = 0; i < 4; i++) {               // A: 2048 quads
            int idx = t + 512 * i;
            int r = idx >> 4, q = idx & 15;
            const char* src = xt + (size_t)bs[r] * 1024 + kc * 256 + q * 16;
            uint32_t d = abase + (uint32_t)(r * 16 + (q ^ ((r & 7) << 1))) * 16u;
            cp16(d, src, (r < mrows) ? 16 : 0);
        }
        const uint32_t bbase = sb + 2 * ABYTES + buf * BBYTES;
#pragma unroll
        for (int i = 0; i < 8; i++) {               // B: 4096 quads
            int idx = t + 512 * i;
            int r = idx >> 4, q = idx & 15;
            const char* src = wt + (size_t)r * 1024 + kc * 256 + q * 16;
            cp16(bbase + (uint32_t)(r * 16 + (q ^ ((r & 7) << 1))) * 16u, src, 16);
        }
    };

    float acc[2][8][4];
#pragma unroll
    for (int im = 0; im < 2; im++)
#pragma unroll
        for (int in = 0; in < 8; in++)
#pragma unroll
            for (int c = 0; c < 4; c++) acc[im][in][c] = 0.f;

    issue(0, 0);
    CP_COMMIT();

    const int sw   = g << 1;
    const int qsub = tg >> 1;
    const int bsel = (tg & 1) * 8;

#pragma unroll 1
    for (int kc = 0; kc < NCHUNK; kc++) {
        const int buf = kc & 1;
        CP_WAIT0();
        __syncthreads();
        if (kc + 1 < NCHUNK) { issue(kc + 1, buf ^ 1); CP_COMMIT(); }

        const char* Ab = smraw + buf * ABYTES;
        const char* Bb = smraw + 2 * ABYTES + buf * BBYTES;

#pragma unroll
        for (int ks = 0; ks < 8; ks++) {
            const int qoff = ((ks * 2 + qsub) ^ sw) * 16 + bsel;
            uint2 U[2], V[2];
#pragma unroll
            for (int im = 0; im < 2; im++) {
                const char* ap = Ab + (wm * 32 + im * 16 + g) * 256 + qoff;
                U[im] = *(const uint2*)ap;
                V[im] = *(const uint2*)(ap + 2048);
            }
#pragma unroll
            for (int in = 0; in < 8; in++) {
                uint2 W = *(const uint2*)(Bb + (wn * 64 + in * 8 + g) * 256 + qoff);
                mma_f16(acc[0][in], U[0].x, V[0].x, U[0].y, V[0].y, W.x, W.y);
                mma_f16(acc[1][in], U[1].x, V[1].x, U[1].y, V[1].y, W.x, W.y);
            }
        }
        __syncthreads();
    }

    // epilogue: w * (acc + bias) -> fp16 slot-indexed scratch (deterministic)
    const float* bias = (mat ? lb : mb) + e * ACT;
    float2 bv[8];
#pragma unroll
    for (int in = 0; in < 8; in++) {
        int c = wn * 64 + in * 8 + 2 * tg;
        bv[in] = make_float2(__ldg(bias + c), __ldg(bias + c + 1));
    }
#pragma unroll
    for (int im = 0; im < 2; im++) {
#pragma unroll
        for (int half = 0; half < 2; half++) {
            int r = wm * 32 + im * 16 + half * 8 + g;
            if (r < mrows) {
                float w = ws[r];
                __half* dst = g_scr + ((size_t)(mat * 4 + ss[r]) * BATCH + bs[r]) * ACT
                            + wn * 64 + 2 * tg;
#pragma unroll
                for (int in = 0; in < 8; in++) {
                    float ox = w * (acc[im][in][half * 2 + 0] + bv[in].x);
                    float oy = w * (acc[im][in][half * 2 + 1] + bv[in].y);
                    *(__half2*)(dst + in * 8) = __floats2half2_rn(ox, oy);
                }
            }
        }
    }
}

// ---------------- kernel 3: combine slots (fp16 scratch), tanh squash ----------------
__global__ void __launch_bounds__(256) finalize_kernel(float* __restrict__ out) {
    const size_t N8 = (size_t)BATCH * ACT / 8;
    const size_t N4 = (size_t)BATCH * ACT / 4;
    size_t i = (size_t)blockIdx.x * 256 + threadIdx.x;
    if (i >= N8) return;
    const uint4* s = (const uint4*)g_scr;
    float4* out4 = (float4*)out;

    float acc[8];
#pragma unroll
    for (int j = 0; j < 8; j++) acc[j] = 0.f;
#pragma unroll
    for (int sl = 0; sl < 4; sl++) {
        uint4 u = s[sl * N8 + i];
        float2 f0 = __half22float2(*(__half2*)&u.x);
        float2 f1 = __half22float2(*(__half2*)&u.y);
        float2 f2 = __half22float2(*(__half2*)&u.z);
        float2 f3 = __half22float2(*(__half2*)&u.w);
        acc[0] += f0.x; acc[1] += f0.y; acc[2] += f1.x; acc[3] += f1.y;
        acc[4] += f2.x; acc[5] += f2.y; acc[6] += f3.x; acc[7] += f3.y;
    }
    out4[2 * i]     = make_float4(acc[0], acc[1], acc[2], acc[3]);
    out4[2 * i + 1] = make_float4(acc[4], acc[5], acc[6], acc[7]);

#pragma unroll
    for (int j = 0; j < 8; j++) acc[j] = 0.f;
#pragma unroll
    for (int sl = 4; sl < 8; sl++) {
        uint4 u = s[sl * N8 + i];
        float2 f0 = __half22float2(*(__half2*)&u.x);
        float2 f1 = __half22float2(*(__half2*)&u.y);
        float2 f2 = __half22float2(*(__half2*)&u.z);
        float2 f3 = __half22float2(*(__half2*)&u.w);
        acc[0] += f0.x; acc[1] += f0.y; acc[2] += f1.x; acc[3] += f1.y;
        acc[4] += f2.x; acc[5] += f2.y; acc[6] += f3.x; acc[7] += f3.y;
    }
#pragma unroll
    for (int j = 0; j < 8; j++) acc[j] = -5.f + 3.5f * (tanhf(acc[j]) + 1.f);
    out4[N4 + 2 * i]     = make_float4(acc[0], acc[1], acc[2], acc[3]);
    out4[N4 + 2 * i + 1] = make_float4(acc[4], acc[5], acc[6], acc[7]);
}

// ---------------- launch ----------------
extern "C" void kernel_launch(void* const* d_in, const int* in_sizes, int n_in,
                              void* d_out, int out_size) {
    const float* x  = (const float*)d_in[0];
    const float* rw = (const float*)d_in[1];
    const float* rb = (const float*)d_in[2];
    const float* mw = (const float*)d_in[3];
    const float* mb = (const float*)d_in[4];
    const float* lw = (const float*)d_in[5];
    const float* lb = (const float*)d_in[6];
    float* out = (float*)d_out;

    cudaFuncSetAttribute(expert_mma_kernel,
                         cudaFuncAttributeMaxDynamicSharedMemorySize, DYN_SMEM);

    void* cntp = nullptr;
    cudaGetSymbolAddress(&cntp, g_cnt);
    cudaMemsetAsync(cntp, 0, sizeof(int) * NE);

    wconv_kernel<<<1024, 256>>>(mw, lw);
    router_kernel<<<BATCH / 4, 128>>>(x, rw, rb);

    dim3 g2(MAX_CHUNKS, NE, 2);
    expert_mma_kernel<<<g2, 512, DYN_SMEM>>>(mb, lb);

    finalize_kernel<<<(BATCH * ACT / 8 + 255) / 256, 256>>>(out);
}

// round 10
// speedup vs baseline: 1.3482x; 1.1653x over previous
#include <cuda_runtime.h>
#include <cuda_fp16.h>
#include <math.h>
#include <cstdint>

#define BATCH 16384
#define OBS   512
#define ACT   256
#define NE    16
#define TOPK  4
#define TILE_M 128
#define NCHUNK 4                       // K chunks of 128
#define MAX_CHUNKS (BATCH / TILE_M)

// ---------------- static device scratch ----------------
__device__ int    g_cnt[NE];
__device__ int    g_ridx[NE * BATCH];
__device__ float  g_w[NE * BATCH];
__device__ __half g_scr[(size_t)2 * 4 * BATCH * ACT];     // fp16 scratch [mat][slot][BATCH][ACT]
__device__ __half g_xt[(size_t)BATCH * OBS];              // fp16, k-permuted x
__device__ __half g_wt[(size_t)2 * NE * ACT * OBS];       // fp16, k-permuted weights

struct alignas(16) H8 { __half2 a, b, c, d; };

// m16n8k16 fp16 mma, fp32 accumulate
__device__ __forceinline__ void mma_f16(float* c,
                                        uint32_t a0, uint32_t a1, uint32_t a2, uint32_t a3,
                                        uint32_t b0, uint32_t b1) {
    asm volatile(
        "mma.sync.aligned.m16n8k16.row.col.f32.f16.f16.f32 "
        "{%0,%1,%2,%3}, {%4,%5,%6,%7}, {%8,%9}, {%0,%1,%2,%3};"
        : "+f"(c[0]), "+f"(c[1]), "+f"(c[2]), "+f"(c[3])
        : "r"(a0), "r"(a1), "r"(a2), "r"(a3), "r"(b0), "r"(b1));
}

__device__ __forceinline__ uint32_t smem_u32(const void* p) {
    uint32_t a;
    asm("{ .reg .u64 t; cvta.to.shared.u64 t, %1; cvt.u32.u64 %0, t; }" : "=r"(a) : "l"(p));
    return a;
}
__device__ __forceinline__ void cp16(uint32_t dst, const void* src, int sz) {
    asm volatile("cp.async.cg.shared.global [%0], [%1], 16, %2;"
                 :: "r"(dst), "l"(src), "r"(sz) : "memory");
}
#define CP_COMMIT() asm volatile("cp.async.commit_group;" ::: "memory")
#define CP_WAIT0()  asm volatile("cp.async.wait_group 0;" ::: "memory")

// pack a 16-k group (4 float4s, k contiguous) into permuted fp16:
// [k0,k1,k8,k9, k2,k3,k10,k11, k4,k5,k12,k13, k6,k7,k14,k15]
__device__ __forceinline__ void pack_group(float4 v0, float4 v1, float4 v2, float4 v3,
                                           H8* dst) {
    H8 o0, o1;
    o0.a = __floats2half2_rn(v0.x, v0.y); o0.b = __floats2half2_rn(v2.x, v2.y);
    o0.c = __floats2half2_rn(v0.z, v0.w); o0.d = __floats2half2_rn(v2.z, v2.w);
    o1.a = __floats2half2_rn(v1.x, v1.y); o1.b = __floats2half2_rn(v3.x, v3.y);
    o1.c = __floats2half2_rn(v1.z, v1.w); o1.d = __floats2half2_rn(v3.z, v3.w);
    dst[0] = o0; dst[1] = o1;
}

// ---------------- kernel 1: fused prep ----------------
// bx [0,4096):     router, 1 row/warp (Round-4 structure; measured fastest)
// bx [4096,8192):  x -> fp16 permuted pack (streaming)
// bx [8192,10240): weight -> fp16 permuted pack (streaming)
__global__ void __launch_bounds__(128) prep_kernel(const float* __restrict__ x,
                                                   const float* __restrict__ rw,
                                                   const float* __restrict__ rb,
                                                   const float* __restrict__ mw,
                                                   const float* __restrict__ lw) {
    const int bx = blockIdx.x;

    if (bx >= 8192) {
        // ---- weight convert: one 16-k group per thread ----
        int flat = (bx - 8192) * 128 + threadIdx.x;  // 262144 = 8192 rows x 32 groups
        int g16 = flat & 31;
        int rowp = flat >> 5;                        // mat*4096 + row
        int mat = rowp >> 12;
        const float4* s4 = (const float4*)((mat ? lw : mw) + (size_t)(rowp & 4095) * OBS + g16 * 16);
        pack_group(s4[0], s4[1], s4[2], s4[3], (H8*)(g_wt + (size_t)rowp * OBS + g16 * 16));
        return;
    }
    if (bx >= 4096) {
        // ---- x convert: one 16-k group per thread ----
        int flat = (bx - 4096) * 128 + threadIdx.x;  // 524288 = 16384 rows x 32 groups
        int g16 = flat & 31;
        int row = flat >> 5;
        const float4* s4 = (const float4*)(x + (size_t)row * OBS + g16 * 16);
        pack_group(s4[0], s4[1], s4[2], s4[3], (H8*)(g_xt + (size_t)row * OBS + g16 * 16));
        return;
    }

    // ---- router: 1 row per warp (Round-4 structure) ----
    const int warp = threadIdx.x >> 5;
    const int lane = threadIdx.x & 31;
    const int b = bx * 4 + warp;

    const float4* x4 = (const float4*)x;
    float4 xa[4];
#pragma unroll
    for (int i = 0; i < 4; i++) xa[i] = x4[(size_t)b * 128 + lane + 32 * i];

    float logit = 0.f;
#pragma unroll
    for (int e = 0; e < NE; e++) {
        const float4* w4 = (const float4*)rw + e * 128;
        float s = 0.f;
#pragma unroll
        for (int i = 0; i < 4; i++) {
            float4 w = __ldg(w4 + lane + 32 * i);
            s = fmaf(xa[i].x, w.x, fmaf(xa[i].y, w.y, fmaf(xa[i].z, w.z, fmaf(xa[i].w, w.w, s))));
        }
#pragma unroll
        for (int off = 16; off; off >>= 1) s += __shfl_xor_sync(0xffffffffu, s, off);
        if (lane == e) logit = s + rb[e];
    }

    float v = (lane < NE) ? logit : -1e30f;
    float m = v;
#pragma unroll
    for (int off = 16; off; off >>= 1) m = fmaxf(m, __shfl_xor_sync(0xffffffffu, m, off));
    float p = (lane < NE) ? expf(v - m) : 0.f;
    float s = p;
#pragma unroll
    for (int off = 16; off; off >>= 1) s += __shfl_xor_sync(0xffffffffu, s, off);
    float prob = p / s;

    float cur = (lane < NE) ? prob : -1.f;
#pragma unroll
    for (int slot = 0; slot < TOPK; slot++) {
        float mx = cur;
#pragma unroll
        for (int off = 16; off; off >>= 1) mx = fmaxf(mx, __shfl_xor_sync(0xffffffffu, mx, off));
        unsigned bal = __ballot_sync(0xffffffffu, cur == mx);
        int sel = __ffs(bal) - 1;
        if (lane == sel) {
            int pos = atomicAdd(&g_cnt[lane], 1);
            g_ridx[lane * BATCH + pos] = b * 4 + slot;
            g_w[lane * BATCH + pos]    = prob;
            cur = -1.f;
        }
    }
}

// ---------------- kernel 2: fp16 mma grouped GEMM, K-chunk 128 ----------------
#define ABYTES 32768u                  // 128 rows x 256 B
#define BBYTES 65536u                  // 256 rows x 256 B
#define DYN_SMEM (2 * (ABYTES + BBYTES))   // 196608

__global__ void __launch_bounds__(512, 1)
expert_mma_kernel(const float* __restrict__ mb, const float* __restrict__ lb) {
    const int e   = blockIdx.y;
    const int mat = blockIdx.z;
    const int n   = g_cnt[e];
    const int start = blockIdx.x * TILE_M;
    if (start >= n) return;
    const int mrows = min(TILE_M, n - start);

    __shared__ int   bs[TILE_M];
    __shared__ int   ss[TILE_M];
    __shared__ float ws[TILE_M];
    extern __shared__ char smraw[];
    const uint32_t sb = smem_u32(smraw);

    const int t = threadIdx.x;
    if (t < TILE_M) {
        if (t < mrows) {
            int entry = g_ridx[e * BATCH + start + t];
            bs[t] = entry >> 2; ss[t] = entry & 3;
            ws[t] = g_w[e * BATCH + start + t];
        } else { bs[t] = 0; ss[t] = 0; ws[t] = 0.f; }
    }
    __syncthreads();

    const char* xt = (const char*)g_xt;
    const char* wt = (const char*)(g_wt + (size_t)((mat * NE + e) * ACT) * OBS);

    const int lane = t & 31;
    const int g  = lane >> 2;
    const int tg = lane & 3;
    const int wid = t >> 5;
    const int wm = wid & 3;
    const int wn = wid >> 2;

    auto issue = [&](int kc, int buf) {
        const uint32_t abase = sb + buf * ABYTES;
#pragma unroll
        for (int i = 0; i < 4; i++) {               // A: 2048 quads
            int idx = t + 512 * i;
            int r = idx >> 4, q = idx & 15;
            const char* src = xt + (size_t)bs[r] * 1024 + kc * 256 + q * 16;
            uint32_t d = abase + (uint32_t)(r * 16 + (q ^ ((r & 7) << 1))) * 16u;
            cp16(d, src, (r < mrows) ? 16 : 0);
        }
        const uint32_t bbase = sb + 2 * ABYTES + buf * BBYTES;
#pragma unroll
        for (int i = 0; i < 8; i++) {               // B: 4096 quads
            int idx = t + 512 * i;
            int r = idx >> 4, q = idx & 15;
            const char* src = wt + (size_t)r * 1024 + kc * 256 + q * 16;
            cp16(bbase + (uint32_t)(r * 16 + (q ^ ((r & 7) << 1))) * 16u, src, 16);
        }
    };

    float acc[2][8][4];
#pragma unroll
    for (int im = 0; im < 2; im++)
#pragma unroll
        for (int in = 0; in < 8; in++)
#pragma unroll
            for (int c = 0; c < 4; c++) acc[im][in][c] = 0.f;

    issue(0, 0);
    CP_COMMIT();

    const int sw   = g << 1;
    const int qsub = tg >> 1;
    const int bsel = (tg & 1) * 8;

#pragma unroll 1
    for (int kc = 0; kc < NCHUNK; kc++) {
        const int buf = kc & 1;
        CP_WAIT0();
        __syncthreads();
        if (kc + 1 < NCHUNK) { issue(kc + 1, buf ^ 1); CP_COMMIT(); }

        const char* Ab = smraw + buf * ABYTES;
        const char* Bb = smraw + 2 * ABYTES + buf * BBYTES;

#pragma unroll
        for (int ks = 0; ks < 8; ks++) {
            const int qoff = ((ks * 2 + qsub) ^ sw) * 16 + bsel;
            uint2 U[2], V[2];
#pragma unroll
            for (int im = 0; im < 2; im++) {
                const char* ap = Ab + (wm * 32 + im * 16 + g) * 256 + qoff;
                U[im] = *(const uint2*)ap;
                V[im] = *(const uint2*)(ap + 2048);
            }
#pragma unroll
            for (int in = 0; in < 8; in++) {
                uint2 W = *(const uint2*)(Bb + (wn * 64 + in * 8 + g) * 256 + qoff);
                mma_f16(acc[0][in], U[0].x, V[0].x, U[0].y, V[0].y, W.x, W.y);
                mma_f16(acc[1][in], U[1].x, V[1].x, U[1].y, V[1].y, W.x, W.y);
            }
        }
        __syncthreads();
    }

    // epilogue: w * (acc + bias) -> fp16 slot-indexed scratch (deterministic)
    const float* bias = (mat ? lb : mb) + e * ACT;
    float2 bv[8];
#pragma unroll
    for (int in = 0; in < 8; in++) {
        int c = wn * 64 + in * 8 + 2 * tg;
        bv[in] = make_float2(__ldg(bias + c), __ldg(bias + c + 1));
    }
#pragma unroll
    for (int im = 0; im < 2; im++) {
#pragma unroll
        for (int half = 0; half < 2; half++) {
            int r = wm * 32 + im * 16 + half * 8 + g;
            if (r < mrows) {
                float w = ws[r];
                __half* dst = g_scr + ((size_t)(mat * 4 + ss[r]) * BATCH + bs[r]) * ACT
                            + wn * 64 + 2 * tg;
#pragma unroll
                for (int in = 0; in < 8; in++) {
                    float ox = w * (acc[im][in][half * 2 + 0] + bv[in].x);
                    float oy = w * (acc[im][in][half * 2 + 1] + bv[in].y);
                    *(__half2*)(dst + in * 8) = __floats2half2_rn(ox, oy);
                }
            }
        }
    }
}

// ---------------- kernel 3: combine slots (fp16 scratch), tanh squash ----------------
__global__ void __launch_bounds__(256) finalize_kernel(float* __restrict__ out) {
    const size_t N8 = (size_t)BATCH * ACT / 8;
    const size_t N4 = (size_t)BATCH * ACT / 4;
    size_t i = (size_t)blockIdx.x * 256 + threadIdx.x;
    if (i >= N8) return;
    const uint4* s = (const uint4*)g_scr;
    float4* out4 = (float4*)out;

    float acc[8];
#pragma unroll
    for (int j = 0; j < 8; j++) acc[j] = 0.f;
#pragma unroll
    for (int sl = 0; sl < 4; sl++) {
        uint4 u = s[sl * N8 + i];
        float2 f0 = __half22float2(*(__half2*)&u.x);
        float2 f1 = __half22float2(*(__half2*)&u.y);
        float2 f2 = __half22float2(*(__half2*)&u.z);
        float2 f3 = __half22float2(*(__half2*)&u.w);
        acc[0] += f0.x; acc[1] += f0.y; acc[2] += f1.x; acc[3] += f1.y;
        acc[4] += f2.x; acc[5] += f2.y; acc[6] += f3.x; acc[7] += f3.y;
    }
    out4[2 * i]     = make_float4(acc[0], acc[1], acc[2], acc[3]);
    out4[2 * i + 1] = make_float4(acc[4], acc[5], acc[6], acc[7]);

#pragma unroll
    for (int j = 0; j < 8; j++) acc[j] = 0.f;
#pragma unroll
    for (int sl = 4; sl < 8; sl++) {
        uint4 u = s[sl * N8 + i];
        float2 f0 = __half22float2(*(__half2*)&u.x);
        float2 f1 = __half22float2(*(__half2*)&u.y);
        float2 f2 = __half22float2(*(__half2*)&u.z);
        float2 f3 = __half22float2(*(__half2*)&u.w);
        acc[0] += f0.x; acc[1] += f0.y; acc[2] += f1.x; acc[3] += f1.y;
        acc[4] += f2.x; acc[5] += f2.y; acc[6] += f3.x; acc[7] += f3.y;
    }
#pragma unroll
    for (int j = 0; j < 8; j++) acc[j] = -5.f + 3.5f * (tanhf(acc[j]) + 1.f);
    out4[N4 + 2 * i]     = make_float4(acc[0], acc[1], acc[2], acc[3]);
    out4[N4 + 2 * i + 1] = make_float4(acc[4], acc[5], acc[6], acc[7]);
}

// ---------------- launch ----------------
extern "C" void kernel_launch(void* const* d_in, const int* in_sizes, int n_in,
                              void* d_out, int out_size) {
    const float* x  = (const float*)d_in[0];
    const float* rw = (const float*)d_in[1];
    const float* rb = (const float*)d_in[2];
    const float* mw = (const float*)d_in[3];
    const float* mb = (const float*)d_in[4];
    const float* lw = (const float*)d_in[5];
    const float* lb = (const float*)d_in[6];
    float* out = (float*)d_out;

    cudaFuncSetAttribute(expert_mma_kernel,
                         cudaFuncAttributeMaxDynamicSharedMemorySize, DYN_SMEM);

    void* cntp = nullptr;
    cudaGetSymbolAddress(&cntp, g_cnt);
    cudaMemsetAsync(cntp, 0, sizeof(int) * NE);

    prep_kernel<<<10240, 128>>>(x, rw, rb, mw, lw);

    dim3 g2(MAX_CHUNKS, NE, 2);
    expert_mma_kernel<<<g2, 512, DYN_SMEM>>>(mb, lb);

    finalize_kernel<<<(BATCH * ACT / 8 + 255) / 256, 256>>>(out);
}

// round 11
// speedup vs baseline: 1.3863x; 1.0283x over previous
#include <cuda_runtime.h>
#include <cuda_fp16.h>
#include <math.h>
#include <cstdint>

#define BATCH 16384
#define OBS   512
#define ACT   256
#define NE    16
#define TOPK  4
#define TILE_M 128
#define NCHUNK 4                       // K chunks of 128
#define MAX_CHUNKS (BATCH / TILE_M)

// ---------------- static device scratch ----------------
__device__ int    g_cnt[NE];
__device__ int    g_ridx[NE * BATCH];
__device__ float  g_w[NE * BATCH];
__device__ __half g_scr[(size_t)2 * 4 * BATCH * ACT];     // fp16 scratch [mat][slot][BATCH][ACT]
__device__ __half g_xt[(size_t)BATCH * OBS];              // fp16, k-permuted x
__device__ __half g_wt[(size_t)2 * NE * ACT * OBS];       // fp16, k-permuted weights

struct alignas(16) H8 { __half2 a, b, c, d; };

// m16n8k16 fp16 mma, fp32 accumulate
__device__ __forceinline__ void mma_f16(float* c,
                                        uint32_t a0, uint32_t a1, uint32_t a2, uint32_t a3,
                                        uint32_t b0, uint32_t b1) {
    asm volatile(
        "mma.sync.aligned.m16n8k16.row.col.f32.f16.f16.f32 "
        "{%0,%1,%2,%3}, {%4,%5,%6,%7}, {%8,%9}, {%0,%1,%2,%3};"
        : "+f"(c[0]), "+f"(c[1]), "+f"(c[2]), "+f"(c[3])
        : "r"(a0), "r"(a1), "r"(a2), "r"(a3), "r"(b0), "r"(b1));
}

__device__ __forceinline__ uint32_t smem_u32(const void* p) {
    uint32_t a;
    asm("{ .reg .u64 t; cvta.to.shared.u64 t, %1; cvt.u32.u64 %0, t; }" : "=r"(a) : "l"(p));
    return a;
}
__device__ __forceinline__ void cp16(uint32_t dst, const void* src, int sz) {
    asm volatile("cp.async.cg.shared.global [%0], [%1], 16, %2;"
                 :: "r"(dst), "l"(src), "r"(sz) : "memory");
}
#define CP_COMMIT() asm volatile("cp.async.commit_group;" ::: "memory")
#define CP_WAIT0()  asm volatile("cp.async.wait_group 0;" ::: "memory")

// pack a 16-k group (4 float4s, k contiguous) into permuted fp16:
// [k0,k1,k8,k9, k2,k3,k10,k11, k4,k5,k12,k13, k6,k7,k14,k15]
__device__ __forceinline__ void pack_group(float4 v0, float4 v1, float4 v2, float4 v3,
                                           H8* dst) {
    H8 o0, o1;
    o0.a = __floats2half2_rn(v0.x, v0.y); o0.b = __floats2half2_rn(v2.x, v2.y);
    o0.c = __floats2half2_rn(v0.z, v0.w); o0.d = __floats2half2_rn(v2.z, v2.w);
    o1.a = __floats2half2_rn(v1.x, v1.y); o1.b = __floats2half2_rn(v3.x, v3.y);
    o1.c = __floats2half2_rn(v1.z, v1.w); o1.d = __floats2half2_rn(v3.z, v3.w);
    dst[0] = o0; dst[1] = o1;
}

// ---------------- kernel 1: fused prep (unchanged from R10 best) ----------------
// bx [0,4096):     router, 1 row/warp
// bx [4096,8192):  x -> fp16 permuted pack (streaming)
// bx [8192,10240): weight -> fp16 permuted pack (streaming)
__global__ void __launch_bounds__(128) prep_kernel(const float* __restrict__ x,
                                                   const float* __restrict__ rw,
                                                   const float* __restrict__ rb,
                                                   const float* __restrict__ mw,
                                                   const float* __restrict__ lw) {
    const int bx = blockIdx.x;

    if (bx >= 8192) {
        int flat = (bx - 8192) * 128 + threadIdx.x;
        int g16 = flat & 31;
        int rowp = flat >> 5;
        int mat = rowp >> 12;
        const float4* s4 = (const float4*)((mat ? lw : mw) + (size_t)(rowp & 4095) * OBS + g16 * 16);
        pack_group(s4[0], s4[1], s4[2], s4[3], (H8*)(g_wt + (size_t)rowp * OBS + g16 * 16));
        return;
    }
    if (bx >= 4096) {
        int flat = (bx - 4096) * 128 + threadIdx.x;
        int g16 = flat & 31;
        int row = flat >> 5;
        const float4* s4 = (const float4*)(x + (size_t)row * OBS + g16 * 16);
        pack_group(s4[0], s4[1], s4[2], s4[3], (H8*)(g_xt + (size_t)row * OBS + g16 * 16));
        return;
    }

    const int warp = threadIdx.x >> 5;
    const int lane = threadIdx.x & 31;
    const int b = bx * 4 + warp;

    const float4* x4 = (const float4*)x;
    float4 xa[4];
#pragma unroll
    for (int i = 0; i < 4; i++) xa[i] = x4[(size_t)b * 128 + lane + 32 * i];

    float logit = 0.f;
#pragma unroll
    for (int e = 0; e < NE; e++) {
        const float4* w4 = (const float4*)rw + e * 128;
        float s = 0.f;
#pragma unroll
        for (int i = 0; i < 4; i++) {
            float4 w = __ldg(w4 + lane + 32 * i);
            s = fmaf(xa[i].x, w.x, fmaf(xa[i].y, w.y, fmaf(xa[i].z, w.z, fmaf(xa[i].w, w.w, s))));
        }
#pragma unroll
        for (int off = 16; off; off >>= 1) s += __shfl_xor_sync(0xffffffffu, s, off);
        if (lane == e) logit = s + rb[e];
    }

    float v = (lane < NE) ? logit : -1e30f;
    float m = v;
#pragma unroll
    for (int off = 16; off; off >>= 1) m = fmaxf(m, __shfl_xor_sync(0xffffffffu, m, off));
    float p = (lane < NE) ? expf(v - m) : 0.f;
    float s = p;
#pragma unroll
    for (int off = 16; off; off >>= 1) s += __shfl_xor_sync(0xffffffffu, s, off);
    float prob = p / s;

    float cur = (lane < NE) ? prob : -1.f;
#pragma unroll
    for (int slot = 0; slot < TOPK; slot++) {
        float mx = cur;
#pragma unroll
        for (int off = 16; off; off >>= 1) mx = fmaxf(mx, __shfl_xor_sync(0xffffffffu, mx, off));
        unsigned bal = __ballot_sync(0xffffffffu, cur == mx);
        int sel = __ffs(bal) - 1;
        if (lane == sel) {
            int pos = atomicAdd(&g_cnt[lane], 1);
            g_ridx[lane * BATCH + pos] = b * 4 + slot;
            g_w[lane * BATCH + pos]    = prob;
            cur = -1.f;
        }
    }
}

// ---------------- kernel 2: fp16 mma grouped GEMM, 8 warps x (64x64) tiles ----------------
#define ABYTES 32768u                  // 128 rows x 256 B
#define BBYTES 65536u                  // 256 rows x 256 B
#define DYN_SMEM (2 * (ABYTES + BBYTES))   // 196608

__global__ void __launch_bounds__(256, 1)
expert_mma_kernel(const float* __restrict__ mb, const float* __restrict__ lb) {
    const int e   = blockIdx.y;
    const int mat = blockIdx.z;
    const int n   = g_cnt[e];
    const int start = blockIdx.x * TILE_M;
    if (start >= n) return;
    const int mrows = min(TILE_M, n - start);

    __shared__ int   bs[TILE_M];
    __shared__ int   ss[TILE_M];
    __shared__ float ws[TILE_M];
    extern __shared__ char smraw[];
    const uint32_t sb = smem_u32(smraw);

    const int t = threadIdx.x;
    if (t < TILE_M) {
        if (t < mrows) {
            int entry = g_ridx[e * BATCH + start + t];
            bs[t] = entry >> 2; ss[t] = entry & 3;
            ws[t] = g_w[e * BATCH + start + t];
        } else { bs[t] = 0; ss[t] = 0; ws[t] = 0.f; }
    }
    __syncthreads();

    const char* xt = (const char*)g_xt;
    const char* wt = (const char*)(g_wt + (size_t)((mat * NE + e) * ACT) * OBS);

    const int lane = t & 31;
    const int g  = lane >> 2;
    const int tg = lane & 3;
    const int wid = t >> 5;        // 0..7
    const int wm = wid & 1;        // warp M tile: rows wm*64..
    const int wn = wid >> 1;       // warp N tile: cols wn*64..

    auto issue = [&](int kc, int buf) {
        const uint32_t abase = sb + buf * ABYTES;
#pragma unroll
        for (int i = 0; i < 8; i++) {               // A: 2048 quads
            int idx = t + 256 * i;
            int r = idx >> 4, q = idx & 15;
            const char* src = xt + (size_t)bs[r] * 1024 + kc * 256 + q * 16;
            uint32_t d = abase + (uint32_t)(r * 16 + (q ^ ((r & 7) << 1))) * 16u;
            cp16(d, src, (r < mrows) ? 16 : 0);
        }
        const uint32_t bbase = sb + 2 * ABYTES + buf * BBYTES;
#pragma unroll
        for (int i = 0; i < 16; i++) {              // B: 4096 quads
            int idx = t + 256 * i;
            int r = idx >> 4, q = idx & 15;
            const char* src = wt + (size_t)r * 1024 + kc * 256 + q * 16;
            cp16(bbase + (uint32_t)(r * 16 + (q ^ ((r & 7) << 1))) * 16u, src, 16);
        }
    };

    float acc[4][8][4];
#pragma unroll
    for (int im = 0; im < 4; im++)
#pragma unroll
        for (int in = 0; in < 8; in++)
#pragma unroll
            for (int c = 0; c < 4; c++) acc[im][in][c] = 0.f;

    issue(0, 0);
    CP_COMMIT();

    const int sw   = g << 1;
    const int qsub = tg >> 1;
    const int bsel = (tg & 1) * 8;

#pragma unroll 1
    for (int kc = 0; kc < NCHUNK; kc++) {
        const int buf = kc & 1;
        CP_WAIT0();
        __syncthreads();
        if (kc + 1 < NCHUNK) { issue(kc + 1, buf ^ 1); CP_COMMIT(); }

        const char* Ab = smraw + buf * ABYTES;
        const char* Bb = smraw + 2 * ABYTES + buf * BBYTES;

#pragma unroll
        for (int ks = 0; ks < 8; ks++) {
            const int qoff = ((ks * 2 + qsub) ^ sw) * 16 + bsel;
            uint2 U[4], V[4];
#pragma unroll
            for (int im = 0; im < 4; im++) {
                const char* ap = Ab + (wm * 64 + im * 16 + g) * 256 + qoff;
                U[im] = *(const uint2*)ap;           // a0, a2
                V[im] = *(const uint2*)(ap + 2048);  // a1, a3 (row+8)
            }
#pragma unroll
            for (int in = 0; in < 8; in++) {
                uint2 W = *(const uint2*)(Bb + (wn * 64 + in * 8 + g) * 256 + qoff);
#pragma unroll
                for (int im = 0; im < 4; im++)
                    mma_f16(acc[im][in], U[im].x, V[im].x, U[im].y, V[im].y, W.x, W.y);
            }
        }
        __syncthreads();
    }

    // epilogue: w * (acc + bias) -> fp16 slot-indexed scratch (deterministic)
    const float* bias = (mat ? lb : mb) + e * ACT;
    float2 bv[8];
#pragma unroll
    for (int in = 0; in < 8; in++) {
        int c = wn * 64 + in * 8 + 2 * tg;
        bv[in] = make_float2(__ldg(bias + c), __ldg(bias + c + 1));
    }
#pragma unroll
    for (int im = 0; im < 4; im++) {
#pragma unroll
        for (int half = 0; half < 2; half++) {
            int r = wm * 64 + im * 16 + half * 8 + g;
            if (r < mrows) {
                float w = ws[r];
                __half* dst = g_scr + ((size_t)(mat * 4 + ss[r]) * BATCH + bs[r]) * ACT
                            + wn * 64 + 2 * tg;
#pragma unroll
                for (int in = 0; in < 8; in++) {
                    float ox = w * (acc[im][in][half * 2 + 0] + bv[in].x);
                    float oy = w * (acc[im][in][half * 2 + 1] + bv[in].y);
                    *(__half2*)(dst + in * 8) = __floats2half2_rn(ox, oy);
                }
            }
        }
    }
}

// ---------------- kernel 3: combine slots (fp16 scratch), tanh squash ----------------
__global__ void __launch_bounds__(256) finalize_kernel(float* __restrict__ out) {
    const size_t N8 = (size_t)BATCH * ACT / 8;
    const size_t N4 = (size_t)BATCH * ACT / 4;
    size_t i = (size_t)blockIdx.x * 256 + threadIdx.x;
    if (i >= N8) return;
    const uint4* s = (const uint4*)g_scr;
    float4* out4 = (float4*)out;

    float acc[8];
#pragma unroll
    for (int j = 0; j < 8; j++) acc[j] = 0.f;
#pragma unroll
    for (int sl = 0; sl < 4; sl++) {
        uint4 u = s[sl * N8 + i];
        float2 f0 = __half22float2(*(__half2*)&u.x);
        float2 f1 = __half22float2(*(__half2*)&u.y);
        float2 f2 = __half22float2(*(__half2*)&u.z);
        float2 f3 = __half22float2(*(__half2*)&u.w);
        acc[0] += f0.x; acc[1] += f0.y; acc[2] += f1.x; acc[3] += f1.y;
        acc[4] += f2.x; acc[5] += f2.y; acc[6] += f3.x; acc[7] += f3.y;
    }
    out4[2 * i]     = make_float4(acc[0], acc[1], acc[2], acc[3]);
    out4[2 * i + 1] = make_float4(acc[4], acc[5], acc[6], acc[7]);

#pragma unroll
    for (int j = 0; j < 8; j++) acc[j] = 0.f;
#pragma unroll
    for (int sl = 4; sl < 8; sl++) {
        uint4 u = s[sl * N8 + i];
        float2 f0 = __half22float2(*(__half2*)&u.x);
        float2 f1 = __half22float2(*(__half2*)&u.y);
        float2 f2 = __half22float2(*(__half2*)&u.z);
        float2 f3 = __half22float2(*(__half2*)&u.w);
        acc[0] += f0.x; acc[1] += f0.y; acc[2] += f1.x; acc[3] += f1.y;
        acc[4] += f2.x; acc[5] += f2.y; acc[6] += f3.x; acc[7] += f3.y;
    }
#pragma unroll
    for (int j = 0; j < 8; j++) acc[j] = -5.f + 3.5f * (tanhf(acc[j]) + 1.f);
    out4[N4 + 2 * i]     = make_float4(acc[0], acc[1], acc[2], acc[3]);
    out4[N4 + 2 * i + 1] = make_float4(acc[4], acc[5], acc[6], acc[7]);
}

// ---------------- launch ----------------
extern "C" void kernel_launch(void* const* d_in, const int* in_sizes, int n_in,
                              void* d_out, int out_size) {
    const float* x  = (const float*)d_in[0];
    const float* rw = (const float*)d_in[1];
    const float* rb = (const float*)d_in[2];
    const float* mw = (const float*)d_in[3];
    const float* mb = (const float*)d_in[4];
    const float* lw = (const float*)d_in[5];
    const float* lb = (const float*)d_in[6];
    float* out = (float*)d_out;

    cudaFuncSetAttribute(expert_mma_kernel,
                         cudaFuncAttributeMaxDynamicSharedMemorySize, DYN_SMEM);

    void* cntp = nullptr;
    cudaGetSymbolAddress(&cntp, g_cnt);
    cudaMemsetAsync(cntp, 0, sizeof(int) * NE);

    prep_kernel<<<10240, 128>>>(x, rw, rb, mw, lw);

    dim3 g2(MAX_CHUNKS, NE, 2);
    expert_mma_kernel<<<g2, 256, DYN_SMEM>>>(mb, lb);

    finalize_kernel<<<(BATCH * ACT / 8 + 255) / 256, 256>>>(out);
}

// round 12
// speedup vs baseline: 1.4224x; 1.0261x over previous
#include <cuda_runtime.h>
#include <cuda_fp16.h>
#include <math.h>
#include <cstdint>

#define BATCH 16384
#define OBS   512
#define ACT   256
#define NE    16
#define TOPK  4
#define TILE_M 128
#define NCHUNK 4                       // K chunks of 128
#define MAX_CHUNKS (BATCH / TILE_M)

// ---------------- static device scratch ----------------
__device__ int    g_cnt[NE];
__device__ int    g_ridx[NE * BATCH];
__device__ float  g_w[NE * BATCH];
__device__ __half g_scr[(size_t)2 * 4 * BATCH * ACT];     // fp16 scratch [mat][slot][BATCH][ACT]
__device__ __half g_xt[(size_t)BATCH * OBS];              // fp16, k-permuted x
__device__ __half g_wt[(size_t)2 * NE * ACT * OBS];       // fp16, k-permuted weights

struct alignas(16) H8 { __half2 a, b, c, d; };

// m16n8k16 fp16 mma, fp32 accumulate
__device__ __forceinline__ void mma_f16(float* c,
                                        uint32_t a0, uint32_t a1, uint32_t a2, uint32_t a3,
                                        uint32_t b0, uint32_t b1) {
    asm volatile(
        "mma.sync.aligned.m16n8k16.row.col.f32.f16.f16.f32 "
        "{%0,%1,%2,%3}, {%4,%5,%6,%7}, {%8,%9}, {%0,%1,%2,%3};"
        : "+f"(c[0]), "+f"(c[1]), "+f"(c[2]), "+f"(c[3])
        : "r"(a0), "r"(a1), "r"(a2), "r"(a3), "r"(b0), "r"(b1));
}

__device__ __forceinline__ uint32_t smem_u32(const void* p) {
    uint32_t a;
    asm("{ .reg .u64 t; cvta.to.shared.u64 t, %1; cvt.u32.u64 %0, t; }" : "=r"(a) : "l"(p));
    return a;
}
__device__ __forceinline__ void cp16(uint32_t dst, const void* src, int sz) {
    asm volatile("cp.async.cg.shared.global [%0], [%1], 16, %2;"
                 :: "r"(dst), "l"(src), "r"(sz) : "memory");
}
#define CP_COMMIT() asm volatile("cp.async.commit_group;" ::: "memory")
#define CP_WAIT0()  asm volatile("cp.async.wait_group 0;" ::: "memory")

// pack a 16-k group (4 float4s, k contiguous) into permuted fp16:
// [k0,k1,k8,k9, k2,k3,k10,k11, k4,k5,k12,k13, k6,k7,k14,k15]
__device__ __forceinline__ void pack_group(float4 v0, float4 v1, float4 v2, float4 v3,
                                           H8* dst) {
    H8 o0, o1;
    o0.a = __floats2half2_rn(v0.x, v0.y); o0.b = __floats2half2_rn(v2.x, v2.y);
    o0.c = __floats2half2_rn(v0.z, v0.w); o0.d = __floats2half2_rn(v2.z, v2.w);
    o1.a = __floats2half2_rn(v1.x, v1.y); o1.b = __floats2half2_rn(v3.x, v3.y);
    o1.c = __floats2half2_rn(v1.z, v1.w); o1.d = __floats2half2_rn(v3.z, v3.w);
    dst[0] = o0; dst[1] = o1;
}

// ---------------- kernel 1: fused prep, classes interleaved by bx % 5 ----------------
// bx%5 in {0,1}: router (4096 blocks), {2,3}: x pack (4096), {4}: weight pack (2048)
__global__ void __launch_bounds__(128) prep_kernel(const float* __restrict__ x,
                                                   const float* __restrict__ rw,
                                                   const float* __restrict__ rb,
                                                   const float* __restrict__ mw,
                                                   const float* __restrict__ lw) {
    const int bx = blockIdx.x;
    const int cls = bx % 5;
    const int grp = bx / 5;            // 0..2047

    if (cls == 4) {
        // ---- weight convert: 2048 blocks ----
        int flat = grp * 128 + threadIdx.x;          // 262144 = 8192 rows x 32 groups
        int g16 = flat & 31;
        int rowp = flat >> 5;
        int mat = rowp >> 12;
        const float4* s4 = (const float4*)((mat ? lw : mw) + (size_t)(rowp & 4095) * OBS + g16 * 16);
        pack_group(s4[0], s4[1], s4[2], s4[3], (H8*)(g_wt + (size_t)rowp * OBS + g16 * 16));
        return;
    }
    if (cls >= 2) {
        // ---- x convert: 4096 blocks (id = grp*2 + (cls-2)) ----
        int xb = grp * 2 + (cls - 2);
        int flat = xb * 128 + threadIdx.x;           // 524288 = 16384 rows x 32 groups
        int g16 = flat & 31;
        int row = flat >> 5;
        const float4* s4 = (const float4*)(x + (size_t)row * OBS + g16 * 16);
        pack_group(s4[0], s4[1], s4[2], s4[3], (H8*)(g_xt + (size_t)row * OBS + g16 * 16));
        return;
    }

    // ---- router: 4096 blocks (id = grp*2 + cls), 1 row/warp ----
    const int rbk = grp * 2 + cls;
    const int warp = threadIdx.x >> 5;
    const int lane = threadIdx.x & 31;
    const int b = rbk * 4 + warp;

    const float4* x4 = (const float4*)x;
    float4 xa[4];
#pragma unroll
    for (int i = 0; i < 4; i++) xa[i] = x4[(size_t)b * 128 + lane + 32 * i];

    float logit = 0.f;
#pragma unroll
    for (int e = 0; e < NE; e++) {
        const float4* w4 = (const float4*)rw + e * 128;
        float s = 0.f;
#pragma unroll
        for (int i = 0; i < 4; i++) {
            float4 w = __ldg(w4 + lane + 32 * i);
            s = fmaf(xa[i].x, w.x, fmaf(xa[i].y, w.y, fmaf(xa[i].z, w.z, fmaf(xa[i].w, w.w, s))));
        }
#pragma unroll
        for (int off = 16; off; off >>= 1) s += __shfl_xor_sync(0xffffffffu, s, off);
        if (lane == e) logit = s + rb[e];
    }

    float v = (lane < NE) ? logit : -1e30f;
    float m = v;
#pragma unroll
    for (int off = 16; off; off >>= 1) m = fmaxf(m, __shfl_xor_sync(0xffffffffu, m, off));
    float p = (lane < NE) ? expf(v - m) : 0.f;
    float s = p;
#pragma unroll
    for (int off = 16; off; off >>= 1) s += __shfl_xor_sync(0xffffffffu, s, off);
    float prob = p / s;

    float cur = (lane < NE) ? prob : -1.f;
#pragma unroll
    for (int slot = 0; slot < TOPK; slot++) {
        float mx = cur;
#pragma unroll
        for (int off = 16; off; off >>= 1) mx = fmaxf(mx, __shfl_xor_sync(0xffffffffu, mx, off));
        unsigned bal = __ballot_sync(0xffffffffu, cur == mx);
        int sel = __ffs(bal) - 1;
        if (lane == sel) {
            int pos = atomicAdd(&g_cnt[lane], 1);
            g_ridx[lane * BATCH + pos] = b * 4 + slot;
            g_w[lane * BATCH + pos]    = prob;
            cur = -1.f;
        }
    }
}

// ---------------- kernel 2: fp16 mma grouped GEMM, 8 warps x (64x64) tiles ----------------
#define ABYTES 32768u                  // 128 rows x 256 B
#define BBYTES 65536u                  // 256 rows x 256 B
#define DYN_SMEM (2 * (ABYTES + BBYTES))   // 196608

__global__ void __launch_bounds__(256, 1)
expert_mma_kernel(const float* __restrict__ mb, const float* __restrict__ lb) {
    const int e   = blockIdx.y;
    const int mat = blockIdx.z;
    const int n   = g_cnt[e];
    const int start = blockIdx.x * TILE_M;
    if (start >= n) return;
    const int mrows = min(TILE_M, n - start);

    __shared__ int   bs[TILE_M];
    __shared__ int   ss[TILE_M];
    __shared__ float ws[TILE_M];
    extern __shared__ char smraw[];
    const uint32_t sb = smem_u32(smraw);

    const int t = threadIdx.x;
    if (t < TILE_M) {
        if (t < mrows) {
            int entry = g_ridx[e * BATCH + start + t];
            bs[t] = entry >> 2; ss[t] = entry & 3;
            ws[t] = g_w[e * BATCH + start + t];
        } else { bs[t] = 0; ss[t] = 0; ws[t] = 0.f; }
    }
    __syncthreads();

    const char* xt = (const char*)g_xt;
    const char* wt = (const char*)(g_wt + (size_t)((mat * NE + e) * ACT) * OBS);

    const int lane = t & 31;
    const int g  = lane >> 2;
    const int tg = lane & 3;
    const int wid = t >> 5;        // 0..7
    const int wm = wid & 1;        // warp M tile: rows wm*64..
    const int wn = wid >> 1;       // warp N tile: cols wn*64..

    auto issue = [&](int kc, int buf) {
        const uint32_t abase = sb + buf * ABYTES;
#pragma unroll
        for (int i = 0; i < 8; i++) {               // A: 2048 quads
            int idx = t + 256 * i;
            int r = idx >> 4, q = idx & 15;
            const char* src = xt + (size_t)bs[r] * 1024 + kc * 256 + q * 16;
            uint32_t d = abase + (uint32_t)(r * 16 + (q ^ ((r & 7) << 1))) * 16u;
            cp16(d, src, (r < mrows) ? 16 : 0);
        }
        const uint32_t bbase = sb + 2 * ABYTES + buf * BBYTES;
#pragma unroll
        for (int i = 0; i < 16; i++) {              // B: 4096 quads
            int idx = t + 256 * i;
            int r = idx >> 4, q = idx & 15;
            const char* src = wt + (size_t)r * 1024 + kc * 256 + q * 16;
            cp16(bbase + (uint32_t)(r * 16 + (q ^ ((r & 7) << 1))) * 16u, src, 16);
        }
    };

    float acc[4][8][4];
#pragma unroll
    for (int im = 0; im < 4; im++)
#pragma unroll
        for (int in = 0; in < 8; in++)
#pragma unroll
            for (int c = 0; c < 4; c++) acc[im][in][c] = 0.f;

    issue(0, 0);
    CP_COMMIT();

    const int sw   = g << 1;
    const int qsub = tg >> 1;
    const int bsel = (tg & 1) * 8;

#pragma unroll 1
    for (int kc = 0; kc < NCHUNK; kc++) {
        const int buf = kc & 1;
        CP_WAIT0();
        __syncthreads();
        if (kc + 1 < NCHUNK) { issue(kc + 1, buf ^ 1); CP_COMMIT(); }

        const char* Ab = smraw + buf * ABYTES;
        const char* Bb = smraw + 2 * ABYTES + buf * BBYTES;

#pragma unroll
        for (int ks = 0; ks < 8; ks++) {
            const int qoff = ((ks * 2 + qsub) ^ sw) * 16 + bsel;
            uint2 U[4], V[4];
#pragma unroll
            for (int im = 0; im < 4; im++) {
                const char* ap = Ab + (wm * 64 + im * 16 + g) * 256 + qoff;
                U[im] = *(const uint2*)ap;           // a0, a2
                V[im] = *(const uint2*)(ap + 2048);  // a1, a3 (row+8)
            }
#pragma unroll
            for (int in = 0; in < 8; in++) {
                uint2 W = *(const uint2*)(Bb + (wn * 64 + in * 8 + g) * 256 + qoff);
#pragma unroll
                for (int im = 0; im < 4; im++)
                    mma_f16(acc[im][in], U[im].x, V[im].x, U[im].y, V[im].y, W.x, W.y);
            }
        }
        __syncthreads();
    }

    // epilogue: w * (acc + bias) -> fp16 slot-indexed scratch (deterministic)
    const float* bias = (mat ? lb : mb) + e * ACT;
    float2 bv[8];
#pragma unroll
    for (int in = 0; in < 8; in++) {
        int c = wn * 64 + in * 8 + 2 * tg;
        bv[in] = make_float2(__ldg(bias + c), __ldg(bias + c + 1));
    }
#pragma unroll
    for (int im = 0; im < 4; im++) {
#pragma unroll
        for (int half = 0; half < 2; half++) {
            int r = wm * 64 + im * 16 + half * 8 + g;
            if (r < mrows) {
                float w = ws[r];
                __half* dst = g_scr + ((size_t)(mat * 4 + ss[r]) * BATCH + bs[r]) * ACT
                            + wn * 64 + 2 * tg;
#pragma unroll
                for (int in = 0; in < 8; in++) {
                    float ox = w * (acc[im][in][half * 2 + 0] + bv[in].x);
                    float oy = w * (acc[im][in][half * 2 + 1] + bv[in].y);
                    *(__half2*)(dst + in * 8) = __floats2half2_rn(ox, oy);
                }
            }
        }
    }
}

// ---------------- kernel 3: combine slots (fp16 scratch), tanh squash ----------------
// each thread handles 2 independent positions for higher MLP
__global__ void __launch_bounds__(256) finalize_kernel(float* __restrict__ out) {
    const size_t N8 = (size_t)BATCH * ACT / 8;
    const size_t N4 = (size_t)BATCH * ACT / 4;
    const size_t base = (size_t)blockIdx.x * 512 + threadIdx.x;
    const uint4* s = (const uint4*)g_scr;
    float4* out4 = (float4*)out;

#pragma unroll
    for (int half = 0; half < 2; half++) {           // half 0: mean (slots 0-3), 1: log_std
        uint4 u[2][4];
#pragma unroll
        for (int v = 0; v < 2; v++) {
            size_t i = base + v * 256;
#pragma unroll
            for (int sl = 0; sl < 4; sl++) u[v][sl] = s[(half * 4 + sl) * N8 + i];
        }
#pragma unroll
        for (int v = 0; v < 2; v++) {
            size_t i = base + v * 256;
            float acc[8];
#pragma unroll
            for (int j = 0; j < 8; j++) acc[j] = 0.f;
#pragma unroll
            for (int sl = 0; sl < 4; sl++) {
                float2 f0 = __half22float2(*(__half2*)&u[v][sl].x);
                float2 f1 = __half22float2(*(__half2*)&u[v][sl].y);
                float2 f2 = __half22float2(*(__half2*)&u[v][sl].z);
                float2 f3 = __half22float2(*(__half2*)&u[v][sl].w);
                acc[0] += f0.x; acc[1] += f0.y; acc[2] += f1.x; acc[3] += f1.y;
                acc[4] += f2.x; acc[5] += f2.y; acc[6] += f3.x; acc[7] += f3.y;
            }
            if (half) {
#pragma unroll
                for (int j = 0; j < 8; j++) acc[j] = -5.f + 3.5f * (tanhf(acc[j]) + 1.f);
            }
            out4[half * N4 + 2 * i]     = make_float4(acc[0], acc[1], acc[2], acc[3]);
            out4[half * N4 + 2 * i + 1] = make_float4(acc[4], acc[5], acc[6], acc[7]);
        }
    }
}

// ---------------- launch ----------------
extern "C" void kernel_launch(void* const* d_in, const int* in_sizes, int n_in,
                              void* d_out, int out_size) {
    const float* x  = (const float*)d_in[0];
    const float* rw = (const float*)d_in[1];
    const float* rb = (const float*)d_in[2];
    const float* mw = (const float*)d_in[3];
    const float* mb = (const float*)d_in[4];
    const float* lw = (const float*)d_in[5];
    const float* lb = (const float*)d_in[6];
    float* out = (float*)d_out;

    cudaFuncSetAttribute(expert_mma_kernel,
                         cudaFuncAttributeMaxDynamicSharedMemorySize, DYN_SMEM);

    void* cntp = nullptr;
    cudaGetSymbolAddress(&cntp, g_cnt);
    cudaMemsetAsync(cntp, 0, sizeof(int) * NE);

    prep_kernel<<<10240, 128>>>(x, rw, rb, mw, lw);

    dim3 g2(MAX_CHUNKS, NE, 2);
    expert_mma_kernel<<<g2, 256, DYN_SMEM>>>(mb, lb);

    finalize_kernel<<<BATCH * ACT / 8 / 512, 256>>>(out);
}